// round 4
// baseline (speedup 1.0000x reference)
#include <cuda_runtime.h>
#include <cstdint>

#define N_PTS 131072
#define DIM   64
#define KCENT 1024
#define TH_GAP 0.25f

// assign tiling
#define ROWS_BLK 256          // M per block
#define NCH      32           // N per chunk
#define NCHUNKS  (KCENT / NCH)   // 32
#define KSTEPS   8            // 64 / k8
#define ASSIGN_BLOCKS (N_PTS / ROWS_BLK)  // 512

// ---------------- device scratch (no allocation allowed) --------------------
__device__ float g_csq[KCENT];
__device__ int   g_ind[N_PTS];
__device__ int   g_counts[KCENT];
__device__ float g_csum[KCENT * DIM];
__device__ float g_cnew[KCENT * DIM];
__device__ float g_loss;
__device__ float g_sum_cs;
__device__ int   g_nflag;
__device__ int   g_flag[N_PTS];
__device__ float g_Ct[KCENT * DIM];    // C transposed: [k][d]

// ---------------- PTX helpers -------------------------------------------------
__device__ __forceinline__ uint32_t f2tf32(float f) {
    uint32_t u;
    asm("cvt.rna.tf32.f32 %0, %1;" : "=r"(u) : "f"(f));
    return u;
}
__device__ __forceinline__ void mma_tf32(float& d0, float& d1, float& d2, float& d3,
                                         uint32_t a0, uint32_t a1, uint32_t a2, uint32_t a3,
                                         uint32_t b0, uint32_t b1) {
    asm volatile(
        "mma.sync.aligned.m16n8k8.row.col.f32.tf32.tf32.f32 "
        "{%0,%1,%2,%3}, {%4,%5,%6,%7}, {%8,%9}, {%0,%1,%2,%3};"
        : "+f"(d0), "+f"(d1), "+f"(d2), "+f"(d3)
        : "r"(a0), "r"(a1), "r"(a2), "r"(a3), "r"(b0), "r"(b1));
}

// ---------------- small kernels -----------------------------------------------
__global__ void zero_kernel() {
    int i = blockIdx.x * blockDim.x + threadIdx.x;
    if (i < KCENT * DIM) g_csum[i] = 0.0f;
    if (i < KCENT)       g_counts[i] = 0;
    if (i == 0)          { g_loss = 0.0f; g_nflag = 0; }
}

__global__ void csq_kernel(const float* __restrict__ C) {
    int k = blockIdx.x * blockDim.x + threadIdx.x;
    if (k < KCENT) {
        float s = 0.0f;
        #pragma unroll
        for (int d = 0; d < DIM; d++) {
            float c = C[d * KCENT + k];
            s = fmaf(c, c, s);
        }
        g_csq[k] = s;
    }
}

__global__ void sumcs_kernel(const float* __restrict__ cluster_size) {
    __shared__ float red[1024];
    int k = threadIdx.x;
    red[k] = cluster_size[k];
    __syncthreads();
    #pragma unroll
    for (int s = 512; s > 0; s >>= 1) {
        if (k < s) red[k] += red[k + s];
        __syncthreads();
    }
    if (k == 0) g_sum_cs = red[0];
}

// transpose C [64][1024] -> Ct [1024][64]
__global__ void prep_Ct(const float* __restrict__ C) {
    __shared__ float t[32][33];
    int tx = threadIdx.x & 31;
    int ty0 = threadIdx.x >> 5;
    int kb = blockIdx.x * 32;
    int db = blockIdx.y * 32;
    #pragma unroll
    for (int yy = 0; yy < 4; yy++) {
        int ty = ty0 + yy * 8;
        t[ty][tx] = C[(db + ty) * KCENT + kb + tx];
    }
    __syncthreads();
    #pragma unroll
    for (int yy = 0; yy < 4; yy++) {
        int ty = ty0 + yy * 8;
        g_Ct[(kb + ty) * DIM + db + tx] = t[tx][ty];
    }
}

// ---------------- assign: tf32 mma + argmax + fused segment sums -------------
// smem (floats): xs[256*68] | cs[32*68] (tf32 bits) | csq[1024] | s_ind[256] | s_flag[256]
#define XS_F   (256 * 68)               // 17408
#define CS_F   (32 * 68)                // 2176
#define OFF_CS   XS_F
#define OFF_CSQ  (OFF_CS + CS_F)        // 19584
#define OFF_IND  (OFF_CSQ + 1024)       // 20608
#define OFF_FLG  (OFF_IND + 256)        // 20864
#define SM_FLOATS (OFF_FLG + 256)       // 21120
#define SM_BYTES  (SM_FLOATS * 4)       // 84480

__global__ void __launch_bounds__(256, 1)
assign_kernel(const float* __restrict__ X) {
    extern __shared__ __align__(16) float sm[];
    float*    xs    = sm;
    uint32_t* csu   = (uint32_t*)(sm + OFF_CS);
    float*    s_csq = sm + OFF_CSQ;
    int*      s_ind = (int*)(sm + OFF_IND);
    int*      s_flg = (int*)(sm + OFF_FLG);

    const int tid  = threadIdx.x;
    const int w    = tid >> 5;
    const int lane = tid & 31;
    const int q    = lane >> 2;    // 0..7
    const int r    = lane & 3;     // 0..3
    const int rb   = blockIdx.x * ROWS_BLK;

    // load X tile (exact f32, padded stride 68)
    const float4* Xv = reinterpret_cast<const float4*>(X + (size_t)rb * DIM);
    #pragma unroll
    for (int i = 0; i < 16; i++) {
        int f = tid + i * 256;       // f < 4096
        int row = f >> 4, j = f & 15;
        *reinterpret_cast<float4*>(&xs[row * 68 + j * 4]) = Xv[f];
    }
    // csq -> smem
    #pragma unroll
    for (int i = 0; i < 4; i++) s_csq[tid + i * 256] = g_csq[tid + i * 256];
    __syncthreads();

    // A fragments held in registers: 2 m-tiles x 8 k-steps x 4 regs
    uint32_t Af[2][KSTEPS][4];
    #pragma unroll
    for (int mt = 0; mt < 2; mt++) {
        int row0 = w * 32 + mt * 16 + q;
        #pragma unroll
        for (int ks = 0; ks < KSTEPS; ks++) {
            int k0 = ks * 8 + r;
            Af[mt][ks][0] = f2tf32(xs[row0 * 68 + k0]);
            Af[mt][ks][1] = f2tf32(xs[(row0 + 8) * 68 + k0]);
            Af[mt][ks][2] = f2tf32(xs[row0 * 68 + k0 + 4]);
            Af[mt][ks][3] = f2tf32(xs[(row0 + 8) * 68 + k0 + 4]);
        }
    }

    // per-thread best state for 4 rows: (mt, row-half)
    float v1[4], v2[4];
    int   i1[4];
    #pragma unroll
    for (int s = 0; s < 4; s++) { v1[s] = -3.402823466e38f; v2[s] = -3.402823466e38f; i1[s] = 0; }

    const float4* Ct4 = reinterpret_cast<const float4*>(g_Ct);

    for (int cc = 0; cc < NCHUNKS; cc++) {
        __syncthreads();
        // load + convert C chunk [32 centroids x 64 dims] to tf32
        #pragma unroll
        for (int i = 0; i < 2; i++) {
            int f = tid + i * 256;       // f < 512
            int n = f >> 4, j = f & 15;
            float4 v = Ct4[(cc * 32 + n) * 16 + j];
            uint4 u;
            u.x = f2tf32(v.x); u.y = f2tf32(v.y); u.z = f2tf32(v.z); u.w = f2tf32(v.w);
            *reinterpret_cast<uint4*>(&csu[n * 68 + j * 4]) = u;
        }
        __syncthreads();

        float acc[2][4][4];
        #pragma unroll
        for (int mt = 0; mt < 2; mt++)
            #pragma unroll
            for (int nt = 0; nt < 4; nt++)
                #pragma unroll
                for (int e = 0; e < 4; e++) acc[mt][nt][e] = 0.0f;

        #pragma unroll
        for (int ks = 0; ks < KSTEPS; ks++) {
            uint32_t b0[4], b1[4];
            #pragma unroll
            for (int nt = 0; nt < 4; nt++) {
                b0[nt] = csu[(nt * 8 + q) * 68 + ks * 8 + r];
                b1[nt] = csu[(nt * 8 + q) * 68 + ks * 8 + r + 4];
            }
            #pragma unroll
            for (int mt = 0; mt < 2; mt++)
                #pragma unroll
                for (int nt = 0; nt < 4; nt++)
                    mma_tf32(acc[mt][nt][0], acc[mt][nt][1], acc[mt][nt][2], acc[mt][nt][3],
                             Af[mt][ks][0], Af[mt][ks][1], Af[mt][ks][2], Af[mt][ks][3],
                             b0[nt], b1[nt]);
        }

        // epilogue: scores + running top-2 per row
        int colbase = cc * NCH;
        #pragma unroll
        for (int nt = 0; nt < 4; nt++) {
            int c0 = colbase + nt * 8 + 2 * r;
            float cq0 = s_csq[c0], cq1 = s_csq[c0 + 1];
            #pragma unroll
            for (int mt = 0; mt < 2; mt++) {
                int s0 = mt * 2, s1 = mt * 2 + 1;
                float sa = fmaf(2.0f, acc[mt][nt][0], -cq0);
                float sb = fmaf(2.0f, acc[mt][nt][1], -cq1);
                float sc = fmaf(2.0f, acc[mt][nt][2], -cq0);
                float sd = fmaf(2.0f, acc[mt][nt][3], -cq1);
                if (sa > v1[s0]) { v2[s0] = v1[s0]; v1[s0] = sa; i1[s0] = c0; }
                else if (sa > v2[s0]) v2[s0] = sa;
                if (sb > v1[s0]) { v2[s0] = v1[s0]; v1[s0] = sb; i1[s0] = c0 + 1; }
                else if (sb > v2[s0]) v2[s0] = sb;
                if (sc > v1[s1]) { v2[s1] = v1[s1]; v1[s1] = sc; i1[s1] = c0; }
                else if (sc > v2[s1]) v2[s1] = sc;
                if (sd > v1[s1]) { v2[s1] = v1[s1]; v1[s1] = sd; i1[s1] = c0 + 1; }
                else if (sd > v2[s1]) v2[s1] = sd;
            }
        }
    }

    // reduce top-2 across the 4 lanes sharing each row
    #pragma unroll
    for (int s = 0; s < 4; s++) {
        float a1 = v1[s], a2 = v2[s];
        int   ai = i1[s];
        #pragma unroll
        for (int off = 1; off <= 2; off <<= 1) {
            float o1 = __shfl_xor_sync(0xffffffffu, a1, off);
            float o2 = __shfl_xor_sync(0xffffffffu, a2, off);
            int   oi = __shfl_xor_sync(0xffffffffu, ai, off);
            if (o1 > a1 || (o1 == a1 && oi < ai)) {
                a2 = fmaxf(a1, o2); a1 = o1; ai = oi;
            } else {
                a2 = fmaxf(a2, fmaxf(o1, -3.402823466e38f));
            }
        }
        if (r == 0) {
            int row = w * 32 + (s >> 1) * 16 + q + (s & 1) * 8;
            s_ind[row] = ai;
            s_flg[row] = (a1 - a2 <= TH_GAP) ? 1 : 0;
        }
    }
    __syncthreads();

    // fused segment sums: warp w handles rows w*32..w*32+31
    #pragma unroll
    for (int rr = 0; rr < 32; rr++) {
        int row = w * 32 + rr;
        int k = s_ind[row];
        if (lane == 0) {
            g_ind[rb + row] = k;
            atomicAdd(&g_counts[k], 1);
            if (s_flg[row]) {
                int pos = atomicAdd(&g_nflag, 1);
                g_flag[pos] = rb + row;
            }
        }
        atomicAdd(&g_csum[k * 64 + lane],      xs[row * 68 + lane]);
        atomicAdd(&g_csum[k * 64 + 32 + lane], xs[row * 68 + 32 + lane]);
    }
}

// ---------------- exact fp32 recheck + correction ----------------------------
__global__ void __launch_bounds__(256)
recheck_kernel(const float* __restrict__ X) {
    __shared__ float fx[32 * 68];
    __shared__ float cz[64 * 68];
    const int tid  = threadIdx.x;
    const int w    = tid >> 5;
    const int lane = tid & 31;
    const int nf   = g_nflag;
    const float4* Ct4 = reinterpret_cast<const float4*>(g_Ct);

    for (int tile = blockIdx.x; tile * 32 < nf; tile += gridDim.x) {
        int base = tile * 32;
        int npts = nf - base; if (npts > 32) npts = 32;
        __syncthreads();
        // load flagged X rows
        for (int f = tid; f < npts * 16; f += 256) {
            int p = f >> 4, j = f & 15;
            int row = g_flag[base + p];
            *reinterpret_cast<float4*>(&fx[p * 68 + j * 4]) =
                *reinterpret_cast<const float4*>(X + (size_t)row * 64 + j * 4);
        }

        float bv[4];
        int   bk[4];
        #pragma unroll
        for (int ii = 0; ii < 4; ii++) { bv[ii] = -3.402823466e38f; bk[ii] = 0x7fffffff; }

        for (int ch = 0; ch < 16; ch++) {
            __syncthreads();
            #pragma unroll
            for (int i = 0; i < 4; i++) {
                int f = tid + i * 256;   // f < 1024
                int n = f >> 4, j = f & 15;
                *reinterpret_cast<float4*>(&cz[n * 68 + j * 4]) = Ct4[(ch * 64 + n) * 16 + j];
            }
            __syncthreads();
            #pragma unroll
            for (int ii = 0; ii < 4; ii++) {
                int p = w * 4 + ii;
                if (p >= npts) continue;
                float s0 = 0.0f, s1 = 0.0f;
                #pragma unroll
                for (int d4 = 0; d4 < 16; d4++) {
                    float4 a  = *reinterpret_cast<const float4*>(&fx[p * 68 + d4 * 4]);
                    float4 b0 = *reinterpret_cast<const float4*>(&cz[lane * 68 + d4 * 4]);
                    float4 b1 = *reinterpret_cast<const float4*>(&cz[(lane + 32) * 68 + d4 * 4]);
                    s0 = fmaf(a.x, b0.x, s0); s0 = fmaf(a.y, b0.y, s0);
                    s0 = fmaf(a.z, b0.z, s0); s0 = fmaf(a.w, b0.w, s0);
                    s1 = fmaf(a.x, b1.x, s1); s1 = fmaf(a.y, b1.y, s1);
                    s1 = fmaf(a.z, b1.z, s1); s1 = fmaf(a.w, b1.w, s1);
                }
                int c0 = ch * 64 + lane;
                s0 = fmaf(2.0f, s0, -g_csq[c0]);
                s1 = fmaf(2.0f, s1, -g_csq[c0 + 32]);
                if (s0 > bv[ii]) { bv[ii] = s0; bk[ii] = c0; }
                if (s1 > bv[ii]) { bv[ii] = s1; bk[ii] = c0 + 32; }
            }
        }

        #pragma unroll
        for (int ii = 0; ii < 4; ii++) {
            int p = w * 4 + ii;
            float v = bv[ii];
            int   k = bk[ii];
            #pragma unroll
            for (int off = 16; off > 0; off >>= 1) {
                float ov = __shfl_xor_sync(0xffffffffu, v, off);
                int   ok = __shfl_xor_sync(0xffffffffu, k, off);
                if (ov > v || (ov == v && ok < k)) { v = ov; k = ok; }
            }
            if (p >= npts) continue;
            int row = g_flag[base + p];
            int oldk = g_ind[row];
            if (k != oldk) {
                if (lane == 0) {
                    g_ind[row] = k;
                    atomicAdd(&g_counts[oldk], -1);
                    atomicAdd(&g_counts[k], 1);
                }
                float xa = fx[p * 68 + lane];
                float xb = fx[p * 68 + 32 + lane];
                atomicAdd(&g_csum[oldk * 64 + lane], -xa);
                atomicAdd(&g_csum[k * 64 + lane],     xa);
                atomicAdd(&g_csum[oldk * 64 + 32 + lane], -xb);
                atomicAdd(&g_csum[k * 64 + 32 + lane],     xb);
            }
        }
    }
}

// ---------------- EMA update + normalize (parallel) --------------------------
__global__ void update2_kernel(const float* __restrict__ cluster_size,
                               const float* __restrict__ cavg) {
    int i = blockIdx.x * blockDim.x + threadIdx.x;
    int k = i >> 6;
    int d = i & 63;
    float n = 0.99f * g_sum_cs + 0.01f * (float)N_PTS;
    float csz = 0.99f * cluster_size[k] + 0.01f * (float)g_counts[k];
    float cs = (csz + 1e-5f) / (n + (float)KCENT * 1e-5f) * n;
    float avg_new = 0.99f * cavg[d * KCENT + k] + 0.01f * g_csum[i];
    g_cnew[i] = avg_new / cs;
}

// ---------------- gather + loss ------------------------------------------------
__global__ void gather_kernel(const float* __restrict__ X, float* __restrict__ out) {
    float lsum = 0.0f;
    const int stride = gridDim.x * blockDim.x;
    const float4* Xv = reinterpret_cast<const float4*>(X);
    float4* Ov = reinterpret_cast<float4*>(out);
    for (int i = blockIdx.x * blockDim.x + threadIdx.x; i < N_PTS * DIM / 4; i += stride) {
        int n  = i >> 4;
        int d4 = (i & 15) * 4;
        float4 q = *reinterpret_cast<const float4*>(&g_cnew[g_ind[n] * 64 + d4]);
        float4 x = Xv[i];
        float4 o;
        o.x = x.x + (q.x - x.x);
        o.y = x.y + (q.y - x.y);
        o.z = x.z + (q.z - x.z);
        o.w = x.w + (q.w - x.w);
        Ov[i] = o;
        float dx = x.x - q.x, dy = x.y - q.y, dz = x.z - q.z, dw = x.w - q.w;
        lsum = fmaf(dx, dx, lsum);
        lsum = fmaf(dy, dy, lsum);
        lsum = fmaf(dz, dz, lsum);
        lsum = fmaf(dw, dw, lsum);
    }
    __shared__ float red[256];
    red[threadIdx.x] = lsum;
    __syncthreads();
    #pragma unroll
    for (int s = 128; s > 0; s >>= 1) {
        if (threadIdx.x < s) red[threadIdx.x] += red[threadIdx.x + s];
        __syncthreads();
    }
    if (threadIdx.x == 0) atomicAdd(&g_loss, red[0]);
}

__global__ void finalize_kernel(float* out, int out_size) {
    float loss = g_loss * (1.0f / 8388608.0f);   // 1/(N*D), exact
    for (int i = N_PTS * DIM; i < out_size; i++) out[i] = loss;
}

// -----------------------------------------------------------------------------
extern "C" void kernel_launch(void* const* d_in, const int* in_sizes, int n_in,
                              void* d_out, int out_size) {
    const float* x             = (const float*)d_in[0];  // [N, D]
    const float* centroids     = (const float*)d_in[1];  // [D, K]
    const float* cluster_size  = (const float*)d_in[2];  // [K]
    const float* centroids_avg = (const float*)d_in[3];  // [D, K]
    float* out = (float*)d_out;

    cudaFuncSetAttribute(assign_kernel,
                         cudaFuncAttributeMaxDynamicSharedMemorySize, SM_BYTES);

    zero_kernel<<<(KCENT * DIM + 255) / 256, 256>>>();
    csq_kernel<<<KCENT / 256, 256>>>(centroids);
    sumcs_kernel<<<1, 1024>>>(cluster_size);
    prep_Ct<<<dim3(32, 2), 256>>>(centroids);
    assign_kernel<<<ASSIGN_BLOCKS, 256, SM_BYTES>>>(x);
    recheck_kernel<<<256, 256>>>(x);
    update2_kernel<<<KCENT * DIM / 256, 256>>>(cluster_size, centroids_avg);
    gather_kernel<<<2048, 256>>>(x, out);
    finalize_kernel<<<1, 1>>>(out, out_size);
}